// round 6
// baseline (speedup 1.0000x reference)
#include <cuda_runtime.h>
#include <cuda_bf16.h>
#include <cstdint>

// ----------------------------------------------------------------------------
// GNNLayer: out = relu(x @ W^T + b); out[col[e],0] += x[e,0]
// Pure-bf16 mma.sync GEMM; x and W pre-split into bf16 hi/lo device globals.
// ----------------------------------------------------------------------------

#define IN_DIM  512
#define OUT_DIM 512
#define MAXROWS 100128          // 100000 rows + padding (tile overrun safety)
#define BM      128
#define BN      128
#define BK      32
#define NCHUNK  (IN_DIM / BK)   // 16
#define THREADS 256

// smem: rows padded to 80 bytes (32 bf16 = 64B + 16B pad) -> ldmatrix conflict-free
#define ROWB    80
#define A_HI    0
#define A_LO    (BM * ROWB)
#define B_HI    (2 * BM * ROWB)
#define B_LO    (3 * BM * ROWB)
#define STAGE   (4 * BM * ROWB)      // 40960
#define SM_TOTAL (2 * STAGE)         // 81920

// Pre-split operands (BSS, zero-initialized; rows >= M stay zero)
__device__ __nv_bfloat16 g_Whi[OUT_DIM * IN_DIM];
__device__ __nv_bfloat16 g_Wlo[OUT_DIM * IN_DIM];
__device__ __nv_bfloat16 g_xhi[MAXROWS * IN_DIM];
__device__ __nv_bfloat16 g_xlo[MAXROWS * IN_DIM];

__device__ __forceinline__ uint32_t smem_u32(const void* p) {
    uint32_t a;
    asm("{ .reg .u64 t; cvta.to.shared.u64 t, %1; cvt.u32.u64 %0, t; }" : "=r"(a) : "l"(p));
    return a;
}
__device__ __forceinline__ void ldx4(uint32_t r[4], uint32_t addr) {
    asm volatile("ldmatrix.sync.aligned.m8n8.x4.shared.b16 {%0,%1,%2,%3}, [%4];"
                 : "=r"(r[0]), "=r"(r[1]), "=r"(r[2]), "=r"(r[3]) : "r"(addr));
}
__device__ __forceinline__ void ldx2(uint32_t r[2], uint32_t addr) {
    asm volatile("ldmatrix.sync.aligned.m8n8.x2.shared.b16 {%0,%1}, [%2];"
                 : "=r"(r[0]), "=r"(r[1]) : "r"(addr));
}
__device__ __forceinline__ void mma16816(float c[4], const uint32_t a[4], const uint32_t b[2]) {
    asm volatile("mma.sync.aligned.m16n8k16.row.col.f32.bf16.bf16.f32 "
                 "{%0,%1,%2,%3}, {%4,%5,%6,%7}, {%8,%9}, {%0,%1,%2,%3};"
                 : "+f"(c[0]), "+f"(c[1]), "+f"(c[2]), "+f"(c[3])
                 : "r"(a[0]), "r"(a[1]), "r"(a[2]), "r"(a[3]), "r"(b[0]), "r"(b[1]));
}
__device__ __forceinline__ void cp16(uint32_t dst, const void* src) {
    asm volatile("cp.async.cg.shared.global [%0], [%1], 16;"
                 :: "r"(dst), "l"(__cvta_generic_to_global(src)));
}

// ---------------- prep: split W and x into bf16 hi/lo ------------------------
__global__ void split_W_kernel(const float* __restrict__ W) {
    int i = blockIdx.x * blockDim.x + threadIdx.x;
    if (i < OUT_DIM * IN_DIM) {
        float v = W[i];
        __nv_bfloat16 hi = __float2bfloat16_rn(v);
        g_Whi[i] = hi;
        g_Wlo[i] = __float2bfloat16_rn(v - __bfloat162float(hi));
    }
}

__global__ __launch_bounds__(256)
void split_x_kernel(const float* __restrict__ x, int n4) {   // n4 = M*512/4
    int i = blockIdx.x * blockDim.x + threadIdx.x;
    if (i < n4) {
        float4 v = reinterpret_cast<const float4*>(x)[i];
        __nv_bfloat16 hx = __float2bfloat16_rn(v.x), hy = __float2bfloat16_rn(v.y);
        __nv_bfloat16 hz = __float2bfloat16_rn(v.z), hw = __float2bfloat16_rn(v.w);
        __nv_bfloat16 lx = __float2bfloat16_rn(v.x - __bfloat162float(hx));
        __nv_bfloat16 ly = __float2bfloat16_rn(v.y - __bfloat162float(hy));
        __nv_bfloat16 lz = __float2bfloat16_rn(v.z - __bfloat162float(hz));
        __nv_bfloat16 lw = __float2bfloat16_rn(v.w - __bfloat162float(hw));
        uint2 h, l;
        h.x = ((uint32_t)__bfloat16_as_ushort(hy) << 16) | __bfloat16_as_ushort(hx);
        h.y = ((uint32_t)__bfloat16_as_ushort(hw) << 16) | __bfloat16_as_ushort(hz);
        l.x = ((uint32_t)__bfloat16_as_ushort(ly) << 16) | __bfloat16_as_ushort(lx);
        l.y = ((uint32_t)__bfloat16_as_ushort(lw) << 16) | __bfloat16_as_ushort(lz);
        reinterpret_cast<uint2*>(g_xhi)[i] = h;
        reinterpret_cast<uint2*>(g_xlo)[i] = l;
    }
}

// ---------------- main GEMM kernel (mma.sync, pure bf16) ----------------------
__global__ __launch_bounds__(THREADS)
void gemm_mma_kernel(const float* __restrict__ bias,
                     float* __restrict__ C, int M) {
    extern __shared__ char smem[];
    const uint32_t sb = smem_u32(smem);
    const int tid    = threadIdx.x;
    const int lane   = tid & 31;
    const int wid    = tid >> 5;
    const int warp_m = wid >> 2;          // 0..1
    const int warp_n = wid & 3;           // 0..3
    const int row0   = blockIdx.y * BM;
    const int n0     = blockIdx.x * BN;

    float acc[4][4][4];
    #pragma unroll
    for (int mi = 0; mi < 4; mi++)
        #pragma unroll
        for (int ni = 0; ni < 4; ni++)
            #pragma unroll
            for (int j = 0; j < 4; j++) acc[mi][ni][j] = 0.f;

    // issue one chunk (A hi/lo + B hi/lo) via cp.async, commit as one group
    auto issue = [&](int kt, int st) {
        const int k0 = kt * BK;
        #pragma unroll
        for (int i = 0; i < 2; i++) {
            int idx = i * THREADS + tid;      // 0..511
            int r = idx >> 2;                 // 0..127
            int u = idx & 3;                  // 16B unit
            uint32_t dst = sb + st * STAGE + r * ROWB + u * 16;
            size_t aofs = (size_t)(row0 + r) * IN_DIM + k0 + u * 8;
            size_t bofs = (size_t)(n0 + r)   * IN_DIM + k0 + u * 8;
            cp16(dst + A_HI, g_xhi + aofs);
            cp16(dst + A_LO, g_xlo + aofs);
            cp16(dst + B_HI, g_Whi + bofs);
            cp16(dst + B_LO, g_Wlo + bofs);
        }
        asm volatile("cp.async.commit_group;" ::: "memory");
    };

    // ---- prologue: fill both stages ----------------------------------------
    issue(0, 0);
    issue(1, 1);

    // ---- main loop ----------------------------------------------------------
    for (int kt = 0; kt < NCHUNK; kt++) {
        const int st = kt & 1;
        asm volatile("cp.async.wait_group 1;" ::: "memory");   // group kt done
        __syncthreads();

        const uint32_t sbase = sb + st * STAGE;
        #pragma unroll
        for (int s = 0; s < 2; s++) {
            const int k0 = s * 16;
            const uint32_t acol = (uint32_t)(k0 + ((lane >> 4) << 3)) * 2;
            const uint32_t arow = (uint32_t)(warp_m * 64 + (lane & 15));
            const uint32_t bcol = (uint32_t)(k0 + ((lane >> 3) & 1) * 8) * 2;
            const uint32_t brow = (uint32_t)(warp_n * 32 + (lane & 7));

            uint32_t ah[4][4], al[4][4], bh[4][2], bl[4][2];
            #pragma unroll
            for (int mi = 0; mi < 4; mi++)
                ldx4(ah[mi], sbase + A_HI + (arow + mi * 16) * ROWB + acol);
            #pragma unroll
            for (int ni = 0; ni < 4; ni++)
                ldx2(bh[ni], sbase + B_HI + (brow + ni * 8) * ROWB + bcol);
            // hi x hi
            #pragma unroll
            for (int mi = 0; mi < 4; mi++)
                #pragma unroll
                for (int ni = 0; ni < 4; ni++)
                    mma16816(acc[mi][ni], ah[mi], bh[ni]);
            // lo x hi
            #pragma unroll
            for (int mi = 0; mi < 4; mi++)
                ldx4(al[mi], sbase + A_LO + (arow + mi * 16) * ROWB + acol);
            #pragma unroll
            for (int mi = 0; mi < 4; mi++)
                #pragma unroll
                for (int ni = 0; ni < 4; ni++)
                    mma16816(acc[mi][ni], al[mi], bh[ni]);
            // hi x lo
            #pragma unroll
            for (int ni = 0; ni < 4; ni++)
                ldx2(bl[ni], sbase + B_LO + (brow + ni * 8) * ROWB + bcol);
            #pragma unroll
            for (int mi = 0; mi < 4; mi++)
                #pragma unroll
                for (int ni = 0; ni < 4; ni++)
                    mma16816(acc[mi][ni], ah[mi], bl[ni]);
        }

        __syncthreads();                     // stage st fully consumed
        if (kt + 2 < NCHUNK) issue(kt + 2, st);
        else asm volatile("cp.async.commit_group;" ::: "memory");  // keep group count
    }

    // ---- epilogue: bias + relu + float2 stores ------------------------------
    #pragma unroll
    for (int mi = 0; mi < 4; mi++) {
        int r = row0 + warp_m * 64 + mi * 16 + (lane >> 2);
        #pragma unroll
        for (int ni = 0; ni < 4; ni++) {
            int col = n0 + warp_n * 32 + ni * 8 + (lane & 3) * 2;
            float2 bv = *reinterpret_cast<const float2*>(bias + col);
            if (r < M) {
                float2 o;
                o.x = fmaxf(acc[mi][ni][0] + bv.x, 0.f);
                o.y = fmaxf(acc[mi][ni][1] + bv.y, 0.f);
                *reinterpret_cast<float2*>(C + (size_t)r * OUT_DIM + col) = o;
            }
            if (r + 8 < M) {
                float2 o;
                o.x = fmaxf(acc[mi][ni][2] + bv.x, 0.f);
                o.y = fmaxf(acc[mi][ni][3] + bv.y, 0.f);
                *reinterpret_cast<float2*>(C + (size_t)(r + 8) * OUT_DIM + col) = o;
            }
        }
    }
}

// ---------------- scatter-add on column 0 -------------------------------------
__global__ void scatter_add_col0_kernel(const float* __restrict__ x,
                                        const int* __restrict__ edge_index,
                                        float* __restrict__ out,
                                        int E) {
    int e = blockIdx.x * blockDim.x + threadIdx.x;
    if (e < E) {
        int c = edge_index[E + e];            // row 1 of [2,E] int32
        atomicAdd(&out[(size_t)c * OUT_DIM], x[(size_t)e * IN_DIM]);
    }
}

// ---------------- launch ------------------------------------------------------
extern "C" void kernel_launch(void* const* d_in, const int* in_sizes, int n_in,
                              void* d_out, int out_size) {
    const float* x   = (const float*)d_in[0];
    const int*   ei  = (const int*)d_in[1];
    const float* W   = (const float*)d_in[2];
    const float* b   = (const float*)d_in[3];
    float*       out = (float*)d_out;

    const int M = in_sizes[0] / IN_DIM;
    const int E = in_sizes[1] / 2;

    cudaFuncSetAttribute(gemm_mma_kernel, cudaFuncAttributeMaxDynamicSharedMemorySize, SM_TOTAL);

    split_W_kernel<<<(OUT_DIM * IN_DIM + 255) / 256, 256>>>(W);
    const int n4 = M * IN_DIM / 4;
    split_x_kernel<<<(n4 + 255) / 256, 256>>>(x, n4);

    dim3 grid(OUT_DIM / BN, (M + BM - 1) / BM);   // x = N tiles (L2 reuse of A band)
    gemm_mma_kernel<<<grid, THREADS, SM_TOTAL>>>(b, out, M);

    scatter_add_col0_kernel<<<(E + 255) / 256, 256>>>(x, ei, out, E);
}

// round 7
// speedup vs baseline: 2.7056x; 2.7056x over previous
#include <cuda_runtime.h>
#include <cuda_fp16.h>
#include <cstdint>

// ----------------------------------------------------------------------------
// GNNLayer: out = relu(x @ W^T + b); out[col[e],0] += x[e,0]
// Single-product fp16 mma.sync GEMM (fp32 accum). u=2^-11 -> rel_err ~4e-4.
// ----------------------------------------------------------------------------

#define IN_DIM  512
#define OUT_DIM 512
#define MAXROWS 100224          // 100000 rows + tile padding
#define BM      128
#define BN      128
#define BK      64
#define NCHUNK  (IN_DIM / BK)   // 8
#define THREADS 256

// smem rows padded to 144B (64 fp16 = 128B + 16B pad): 36 words/row -> ldmatrix
// conflict-free (row offsets mod 32 words cycle 0,4,8,...,28).
#define ROWB    144
#define A_OFF   0
#define B_OFF   (BM * ROWB)              // 18432
#define STAGE   (2 * BM * ROWB)          // 36864
#define NSTAGE  3
#define SM_TOTAL (NSTAGE * STAGE)        // 110592

// fp16 operands (BSS zero-init; rows >= M stay zero)
__device__ __half g_Wh[OUT_DIM * IN_DIM];
__device__ __half g_xh[MAXROWS * IN_DIM];

__device__ __forceinline__ uint32_t smem_u32(const void* p) {
    uint32_t a;
    asm("{ .reg .u64 t; cvta.to.shared.u64 t, %1; cvt.u32.u64 %0, t; }" : "=r"(a) : "l"(p));
    return a;
}
__device__ __forceinline__ void ldx4(uint32_t r[4], uint32_t addr) {
    asm volatile("ldmatrix.sync.aligned.m8n8.x4.shared.b16 {%0,%1,%2,%3}, [%4];"
                 : "=r"(r[0]), "=r"(r[1]), "=r"(r[2]), "=r"(r[3]) : "r"(addr));
}
__device__ __forceinline__ void ldx2(uint32_t r[2], uint32_t addr) {
    asm volatile("ldmatrix.sync.aligned.m8n8.x2.shared.b16 {%0,%1}, [%2];"
                 : "=r"(r[0]), "=r"(r[1]) : "r"(addr));
}
__device__ __forceinline__ void mma16816(float c[4], const uint32_t a[4], const uint32_t b[2]) {
    asm volatile("mma.sync.aligned.m16n8k16.row.col.f32.f16.f16.f32 "
                 "{%0,%1,%2,%3}, {%4,%5,%6,%7}, {%8,%9}, {%0,%1,%2,%3};"
                 : "+f"(c[0]), "+f"(c[1]), "+f"(c[2]), "+f"(c[3])
                 : "r"(a[0]), "r"(a[1]), "r"(a[2]), "r"(a[3]), "r"(b[0]), "r"(b[1]));
}
__device__ __forceinline__ void cp16(uint32_t dst, const void* src) {
    asm volatile("cp.async.cg.shared.global [%0], [%1], 16;"
                 :: "r"(dst), "l"(__cvta_generic_to_global(src)));
}

// ---------------- prep: convert W and x to fp16 -------------------------------
__global__ void conv_W_kernel(const float* __restrict__ W) {
    int i = blockIdx.x * blockDim.x + threadIdx.x;
    if (i < OUT_DIM * IN_DIM) g_Wh[i] = __float2half_rn(W[i]);
}

__global__ __launch_bounds__(256)
void conv_x_kernel(const float* __restrict__ x, int n4) {   // n4 = M*512/4
    int i = blockIdx.x * blockDim.x + threadIdx.x;
    if (i < n4) {
        float4 v = reinterpret_cast<const float4*>(x)[i];
        __half2 p0 = __floats2half2_rn(v.x, v.y);
        __half2 p1 = __floats2half2_rn(v.z, v.w);
        uint2 o;
        o.x = *reinterpret_cast<uint32_t*>(&p0);
        o.y = *reinterpret_cast<uint32_t*>(&p1);
        reinterpret_cast<uint2*>(g_xh)[i] = o;
    }
}

// ---------------- main GEMM kernel (mma.sync fp16) -----------------------------
__global__ __launch_bounds__(THREADS)
void gemm_mma_kernel(const float* __restrict__ bias,
                     float* __restrict__ C, int M) {
    extern __shared__ char smem[];
    const uint32_t sb = smem_u32(smem);
    const int tid    = threadIdx.x;
    const int lane   = tid & 31;
    const int wid    = tid >> 5;
    const int warp_m = wid >> 2;          // 0..1
    const int warp_n = wid & 3;           // 0..3
    const int row0   = blockIdx.y * BM;
    const int n0     = blockIdx.x * BN;

    float acc[4][4][4];
    #pragma unroll
    for (int mi = 0; mi < 4; mi++)
        #pragma unroll
        for (int ni = 0; ni < 4; ni++)
            #pragma unroll
            for (int j = 0; j < 4; j++) acc[mi][ni][j] = 0.f;

    // issue one BK=64 chunk: A 128x64 fp16 + B 128x64 fp16, one cp.async group
    auto issue = [&](int kt, int st) {
        const int k0 = kt * BK;
        #pragma unroll
        for (int i = 0; i < 4; i++) {
            int idx = i * THREADS + tid;      // 0..1023
            int r = idx >> 3;                 // 0..127
            int u = idx & 7;                  // 16B unit (8 per 128B row)
            uint32_t dst = sb + st * STAGE + r * ROWB + u * 16;
            cp16(dst + A_OFF, g_xh + (size_t)(row0 + r) * IN_DIM + k0 + u * 8);
            cp16(dst + B_OFF, g_Wh + (size_t)(n0 + r)   * IN_DIM + k0 + u * 8);
        }
        asm volatile("cp.async.commit_group;" ::: "memory");
    };

    // ---- prologue: 2 chunks in flight ---------------------------------------
    issue(0, 0);
    issue(1, 1);

    // ---- main loop (single barrier per chunk) -------------------------------
    for (int kt = 0; kt < NCHUNK; kt++) {
        const int st = kt % NSTAGE;
        asm volatile("cp.async.wait_group 1;" ::: "memory");   // chunk kt ready
        __syncthreads();

        const uint32_t sbase = sb + st * STAGE;
        #pragma unroll
        for (int s = 0; s < 4; s++) {
            const int k0 = s * 16;
            const uint32_t acol = (uint32_t)(k0 + ((lane >> 4) << 3)) * 2;
            const uint32_t arow = (uint32_t)(warp_m * 64 + (lane & 15));
            const uint32_t bcol = (uint32_t)(k0 + ((lane >> 3) & 1) * 8) * 2;
            const uint32_t brow = (uint32_t)(warp_n * 32 + (lane & 7));

            uint32_t af[4][4], bf[4][2];
            #pragma unroll
            for (int mi = 0; mi < 4; mi++)
                ldx4(af[mi], sbase + A_OFF + (arow + mi * 16) * ROWB + acol);
            #pragma unroll
            for (int ni = 0; ni < 4; ni++)
                ldx2(bf[ni], sbase + B_OFF + (brow + ni * 8) * ROWB + bcol);
            #pragma unroll
            for (int mi = 0; mi < 4; mi++)
                #pragma unroll
                for (int ni = 0; ni < 4; ni++)
                    mma16816(acc[mi][ni], af[mi], bf[ni]);
        }

        // stage (kt+2)%NSTAGE differs from stages kt, kt+1 -> safe after the
        // barrier above (all warps are done with chunk kt-1 whose stage we reuse)
        if (kt + 2 < NCHUNK) issue(kt + 2, (kt + 2) % NSTAGE);
        else asm volatile("cp.async.commit_group;" ::: "memory"); // keep group count
    }

    // ---- epilogue: bias + relu + float2 stores ------------------------------
    #pragma unroll
    for (int mi = 0; mi < 4; mi++) {
        int r = row0 + warp_m * 64 + mi * 16 + (lane >> 2);
        #pragma unroll
        for (int ni = 0; ni < 4; ni++) {
            int col = n0 + warp_n * 32 + ni * 8 + (lane & 3) * 2;
            float2 bv = *reinterpret_cast<const float2*>(bias + col);
            if (r < M) {
                float2 o;
                o.x = fmaxf(acc[mi][ni][0] + bv.x, 0.f);
                o.y = fmaxf(acc[mi][ni][1] + bv.y, 0.f);
                *reinterpret_cast<float2*>(C + (size_t)r * OUT_DIM + col) = o;
            }
            if (r + 8 < M) {
                float2 o;
                o.x = fmaxf(acc[mi][ni][2] + bv.x, 0.f);
                o.y = fmaxf(acc[mi][ni][3] + bv.y, 0.f);
                *reinterpret_cast<float2*>(C + (size_t)(r + 8) * OUT_DIM + col) = o;
            }
        }
    }
}

// ---------------- scatter-add on column 0 -------------------------------------
__global__ void scatter_add_col0_kernel(const float* __restrict__ x,
                                        const int* __restrict__ edge_index,
                                        float* __restrict__ out,
                                        int E) {
    int e = blockIdx.x * blockDim.x + threadIdx.x;
    if (e < E) {
        int c = edge_index[E + e];            // row 1 of [2,E] int32
        atomicAdd(&out[(size_t)c * OUT_DIM], x[(size_t)e * IN_DIM]);
    }
}

// ---------------- launch ------------------------------------------------------
extern "C" void kernel_launch(void* const* d_in, const int* in_sizes, int n_in,
                              void* d_out, int out_size) {
    const float* x   = (const float*)d_in[0];
    const int*   ei  = (const int*)d_in[1];
    const float* W   = (const float*)d_in[2];
    const float* b   = (const float*)d_in[3];
    float*       out = (float*)d_out;

    const int M = in_sizes[0] / IN_DIM;
    const int E = in_sizes[1] / 2;

    cudaFuncSetAttribute(gemm_mma_kernel, cudaFuncAttributeMaxDynamicSharedMemorySize, SM_TOTAL);

    conv_W_kernel<<<(OUT_DIM * IN_DIM + 255) / 256, 256>>>(W);
    const int n4 = M * IN_DIM / 4;
    conv_x_kernel<<<(n4 + 255) / 256, 256>>>(x, n4);

    dim3 grid(OUT_DIM / BN, (M + BM - 1) / BM);   // x = N tiles (L2 reuse of A band)
    gemm_mma_kernel<<<grid, THREADS, SM_TOTAL>>>(b, out, M);

    scatter_add_col0_kernel<<<(E + 255) / 256, 256>>>(x, ei, out, E);
}